// round 1
// baseline (speedup 1.0000x reference)
#include <cuda_runtime.h>
#include <math.h>

#define LQ    1024
#define LK    4096
#define NB    8
#define DM    256
#define NH    4
#define HD    (NH*DM)              /* 1024 */
#define Y_SIZE (LQ*NB*DM)          /* 2097152 */

/* ---------------- scratch (device globals; no allocation allowed) -------- */
__device__ float g_qin   [NB*LQ*DM];        /*  8 MB */
__device__ float g_kin   [NB*LK*DM];        /* 32 MB */
__device__ float g_vin   [NB*LK*DM];        /* 32 MB */
__device__ float g_Qh    [NB*LQ*HD];        /* 32 MB */
__device__ float g_Kh    [NB*LK*HD];        /* 128 MB */
__device__ float g_Vh    [NB*LK*HD];        /* 128 MB */
__device__ float g_logits[(long long)NB*NH*LQ*LK]; /* 536 MB */
__device__ float g_O     [NB*LQ*HD];        /* 32 MB */
__device__ float g_fc    [NB*LQ*DM];        /*  8 MB */

/* ---------------- prep: seq-first -> batch-first (+pos adds) ------------- */
__global__ void prep_q_kernel(const float* __restrict__ tgt,
                              const float* __restrict__ qpos) {
    int idx = blockIdx.x * blockDim.x + threadIdx.x;
    int t = idx * 4;
    if (t >= NB*LQ*DM) return;
    int d = t % DM;
    int r = t / DM;          /* b*LQ + q */
    int q = r % LQ;
    int b = r / LQ;
    int src = (q*NB + b)*DM + d;
    float4 a = *(const float4*)(tgt  + src);
    float4 p = *(const float4*)(qpos + src);
    float4 o; o.x = a.x+p.x; o.y = a.y+p.y; o.z = a.z+p.z; o.w = a.w+p.w;
    *(float4*)(g_qin + t) = o;
}

__global__ void prep_kv_kernel(const float* __restrict__ mem,
                               const float* __restrict__ pos) {
    int idx = blockIdx.x * blockDim.x + threadIdx.x;
    int t = idx * 4;
    if (t >= NB*LK*DM) return;
    int d = t % DM;
    int r = t / DM;          /* b*LK + k */
    int k = r % LK;
    int b = r / LK;
    int src = (k*NB + b)*DM + d;
    float4 m = *(const float4*)(mem + src);
    float4 p = *(const float4*)(pos + src);
    float4 o; o.x = m.x+p.x; o.y = m.y+p.y; o.z = m.z+p.z; o.w = m.w+p.w;
    *(float4*)(g_kin + t) = o;
    *(float4*)(g_vin + t) = m;
}

/* ---------------- generic 64x64x16 fp32 tile GEMM ------------------------
 * C[m,n] = alpha * sum_k A[m,k] * (TRANS_B ? B[n,k] : B[k,n])
 * A row-major (lda), B row-major (ldb), C row-major (ldc).
 * All of M, N multiples of 64; K multiple of 16 (guaranteed by the shapes).
 * Batched via blockIdx.z, decomposed as z = z0*NH + z1 (two stride pairs).
 */
template<bool TRANS_B>
__global__ void __launch_bounds__(256)
gemm64(const float* __restrict__ A, const float* __restrict__ B,
       float* __restrict__ C,
       int lda, int ldb, int ldc, int K, float alpha,
       long long sA0, long long sA1,
       long long sB0, long long sB1,
       long long sC0, long long sC1) {
    int z = blockIdx.z;
    int z0 = z / NH, z1 = z % NH;
    A += z0*sA0 + z1*sA1;
    B += z0*sB0 + z1*sB1;
    C += z0*sC0 + z1*sC1;

    const int m0 = blockIdx.y * 64;
    const int n0 = blockIdx.x * 64;

    __shared__ float As[16][68];
    __shared__ float Bs[16][68];

    const int tid = threadIdx.x;       /* 256 */
    const int tx  = tid & 15;
    const int ty  = tid >> 4;

    /* loader mapping: 64 rows x 16 k, each thread one float4 along k */
    const int l_row = tid >> 2;        /* 0..63 */
    const int l_k4  = (tid & 3) * 4;   /* 0,4,8,12 */
    /* NN loader mapping: 16 k x 64 n */
    const int l_bk  = tid >> 4;        /* 0..15 */
    const int l_n4  = (tid & 15) * 4;  /* 0..60 */

    float acc[4][4] = {};

    for (int k0 = 0; k0 < K; k0 += 16) {
        float4 av = *(const float4*)(A + (long long)(m0 + l_row)*lda + k0 + l_k4);
        As[l_k4+0][l_row] = av.x;
        As[l_k4+1][l_row] = av.y;
        As[l_k4+2][l_row] = av.z;
        As[l_k4+3][l_row] = av.w;
        if (TRANS_B) {
            float4 bv = *(const float4*)(B + (long long)(n0 + l_row)*ldb + k0 + l_k4);
            Bs[l_k4+0][l_row] = bv.x;
            Bs[l_k4+1][l_row] = bv.y;
            Bs[l_k4+2][l_row] = bv.z;
            Bs[l_k4+3][l_row] = bv.w;
        } else {
            float4 bv = *(const float4*)(B + (long long)(k0 + l_bk)*ldb + n0 + l_n4);
            Bs[l_bk][l_n4+0] = bv.x;
            Bs[l_bk][l_n4+1] = bv.y;
            Bs[l_bk][l_n4+2] = bv.z;
            Bs[l_bk][l_n4+3] = bv.w;
        }
        __syncthreads();
        #pragma unroll
        for (int kk = 0; kk < 16; kk++) {
            float4 a4 = *(const float4*)&As[kk][ty*4];
            float4 b4 = *(const float4*)&Bs[kk][tx*4];
            float a[4] = {a4.x, a4.y, a4.z, a4.w};
            float b[4] = {b4.x, b4.y, b4.z, b4.w};
            #pragma unroll
            for (int i = 0; i < 4; i++)
                #pragma unroll
                for (int j = 0; j < 4; j++)
                    acc[i][j] += a[i] * b[j];
        }
        __syncthreads();
    }

    #pragma unroll
    for (int i = 0; i < 4; i++) {
        float4 o;
        o.x = alpha*acc[i][0]; o.y = alpha*acc[i][1];
        o.z = alpha*acc[i][2]; o.w = alpha*acc[i][3];
        *(float4*)(C + (long long)(m0 + ty*4 + i)*ldc + n0 + tx*4) = o;
    }
}

/* ---------------- fused softmax (in-place) + head-mean to d_out ---------- */
__device__ __forceinline__ float blk_reduce_max(float v, float* red) {
    red[threadIdx.x] = v; __syncthreads();
    for (int s = 128; s > 0; s >>= 1) {
        if (threadIdx.x < s) red[threadIdx.x] = fmaxf(red[threadIdx.x], red[threadIdx.x+s]);
        __syncthreads();
    }
    float r = red[0]; __syncthreads(); return r;
}
__device__ __forceinline__ float blk_reduce_sum(float v, float* red) {
    red[threadIdx.x] = v; __syncthreads();
    for (int s = 128; s > 0; s >>= 1) {
        if (threadIdx.x < s) red[threadIdx.x] += red[threadIdx.x+s];
        __syncthreads();
    }
    float r = red[0]; __syncthreads(); return r;
}

__global__ void __launch_bounds__(256)
softmax_mean_kernel(float* __restrict__ out_mean) {
    const int row = blockIdx.x;      /* b*LQ + q */
    const int b = row / LQ;
    const int q = row % LQ;
    const int tid = threadIdx.x;
    __shared__ float red[256];

    float mean_acc[LK/256];
    #pragma unroll
    for (int i = 0; i < LK/256; i++) mean_acc[i] = 0.f;

    for (int h = 0; h < NH; h++) {
        float* base = g_logits + ((long long)((b*NH + h)*LQ + q)) * LK;
        float v[LK/256];
        float mx = -1e30f;
        #pragma unroll
        for (int i = 0; i < LK/256; i++) {
            v[i] = base[i*256 + tid];
            mean_acc[i] += v[i];
            mx = fmaxf(mx, v[i]);
        }
        mx = blk_reduce_max(mx, red);
        float s = 0.f;
        #pragma unroll
        for (int i = 0; i < LK/256; i++) { v[i] = expf(v[i] - mx); s += v[i]; }
        s = blk_reduce_sum(s, red);
        float inv = 1.f / s;
        #pragma unroll
        for (int i = 0; i < LK/256; i++) base[i*256 + tid] = v[i] * inv;
    }
    float* mdst = out_mean + (long long)row * LK;
    #pragma unroll
    for (int i = 0; i < LK/256; i++) mdst[i*256 + tid] = mean_acc[i] * 0.25f;
}

/* ---------------- residual + LayerNorm, write y to d_out ----------------- */
__global__ void __launch_bounds__(256)
ln_kernel(const float* __restrict__ tgt,
          const float* __restrict__ gamma,
          const float* __restrict__ beta,
          float* __restrict__ y) {
    const int row = blockIdx.x;      /* b*LQ + q */
    const int b = row / LQ;
    const int q = row % LQ;
    const int d = threadIdx.x;       /* 256 */
    __shared__ float red[256];

    float x = g_fc[row*DM + d] + tgt[(q*NB + b)*DM + d];
    float mu = blk_reduce_sum(x, red) * (1.f/DM);
    float diff = x - mu;
    float var = blk_reduce_sum(diff*diff, red) * (1.f/DM);
    y[(q*NB + b)*DM + d] = diff * rsqrtf(var + 1e-5f) * gamma[d] + beta[d];
}

/* ---------------- launch ------------------------------------------------- */
extern "C" void kernel_launch(void* const* d_in, const int* in_sizes, int n_in,
                              void* d_out, int out_size) {
    const float* tgt  = (const float*)d_in[0];
    const float* mem  = (const float*)d_in[1];
    const float* pos  = (const float*)d_in[2];
    const float* qpos = (const float*)d_in[3];
    const float* Wq   = (const float*)d_in[4];
    const float* Wk   = (const float*)d_in[5];
    const float* Wv   = (const float*)d_in[6];
    const float* Wfc  = (const float*)d_in[7];
    const float* ln_g = (const float*)d_in[8];
    const float* ln_b = (const float*)d_in[9];
    float* out = (float*)d_out;

    float *qin, *kin, *vin, *Qh, *Kh, *Vh, *logits, *O, *fc;
    cudaGetSymbolAddress((void**)&qin,    g_qin);
    cudaGetSymbolAddress((void**)&kin,    g_kin);
    cudaGetSymbolAddress((void**)&vin,    g_vin);
    cudaGetSymbolAddress((void**)&Qh,     g_Qh);
    cudaGetSymbolAddress((void**)&Kh,     g_Kh);
    cudaGetSymbolAddress((void**)&Vh,     g_Vh);
    cudaGetSymbolAddress((void**)&logits, g_logits);
    cudaGetSymbolAddress((void**)&O,      g_O);
    cudaGetSymbolAddress((void**)&fc,     g_fc);

    /* 1) transpose + pos adds */
    prep_q_kernel <<<(NB*LQ*DM/4 + 255)/256, 256>>>(tgt, qpos);
    prep_kv_kernel<<<(NB*LK*DM/4 + 255)/256, 256>>>(mem, pos);

    /* 2) projections (NT): X[M,256] @ W[1024,256]^T */
    {
        dim3 g(HD/64, (NB*LQ)/64, 1);
        gemm64<true><<<g, 256>>>(qin, Wq, Qh, DM, DM, HD, DM, 1.f,
                                 0,0, 0,0, 0,0);
    }
    {
        dim3 g(HD/64, (NB*LK)/64, 1);
        gemm64<true><<<g, 256>>>(kin, Wk, Kh, DM, DM, HD, DM, 1.f,
                                 0,0, 0,0, 0,0);
        gemm64<true><<<g, 256>>>(vin, Wv, Vh, DM, DM, HD, DM, 1.f,
                                 0,0, 0,0, 0,0);
    }

    /* 3) logits = (1/16) * Qh @ Kh^T   (batched over b,h; z = b*NH+h) */
    {
        dim3 g(LK/64, LQ/64, NB*NH);
        gemm64<true><<<g, 256>>>(Qh, Kh, logits,
                                 HD, HD, LK, DM, 0.0625f,
                                 (long long)LQ*HD, DM,          /* A: b, h */
                                 (long long)LK*HD, DM,          /* B: b, h */
                                 (long long)NH*LQ*LK, (long long)LQ*LK); /* C */
    }

    /* 4) softmax in place + head-mean of logits into d_out tail */
    softmax_mean_kernel<<<NB*LQ, 256>>>(out + Y_SIZE);

    /* 5) O = attn @ Vh (NN, batched) */
    {
        dim3 g(DM/64, LQ/64, NB*NH);
        gemm64<false><<<g, 256>>>(logits, Vh, O,
                                  LK, HD, HD, LK, 1.f,
                                  (long long)NH*LQ*LK, (long long)LQ*LK,
                                  (long long)LK*HD, DM,
                                  (long long)LQ*HD, DM);
    }

    /* 6) fc (NT): O[8192,1024] @ Wfc[256,1024]^T */
    {
        dim3 g(DM/64, (NB*LQ)/64, 1);
        gemm64<true><<<g, 256>>>(O, Wfc, fc, HD, HD, DM, HD, 1.f,
                                 0,0, 0,0, 0,0);
    }

    /* 7) residual + LayerNorm -> y at d_out head */
    ln_kernel<<<NB*LQ, 256>>>(tgt, ln_g, ln_b, out);
}

// round 3
// speedup vs baseline: 2.7036x; 2.7036x over previous
#include <cuda_runtime.h>
#include <cuda_bf16.h>
#include <stdint.h>
#include <math.h>

#define LQ    1024
#define LK    4096
#define NB    8
#define DM    256
#define NH    4
#define HD    (NH*DM)              /* 1024 */
#define Y_SIZE (LQ*NB*DM)          /* 2097152 */

/* ---------------- scratch (device globals; no allocation allowed) -------- */
__device__ float g_qin   [NB*LQ*DM];
__device__ float g_kin   [NB*LK*DM];
__device__ float g_vin   [NB*LK*DM];
__device__ float g_Qh    [NB*LQ*HD];
__device__ float g_Kh    [NB*LK*HD];
__device__ float g_Vh    [NB*LK*HD];
__device__ float g_logits[(long long)NB*NH*LQ*LK];
__device__ float g_O     [NB*LQ*HD];
__device__ float g_fc    [NB*LQ*DM];

/* ---------------- prep: seq-first -> batch-first (+pos adds) ------------- */
__global__ void prep_q_kernel(const float* __restrict__ tgt,
                              const float* __restrict__ qpos) {
    int idx = blockIdx.x * blockDim.x + threadIdx.x;
    int t = idx * 4;
    if (t >= NB*LQ*DM) return;
    int d = t % DM;
    int r = t / DM;
    int q = r % LQ;
    int b = r / LQ;
    int src = (q*NB + b)*DM + d;
    float4 a = *(const float4*)(tgt  + src);
    float4 p = *(const float4*)(qpos + src);
    float4 o; o.x = a.x+p.x; o.y = a.y+p.y; o.z = a.z+p.z; o.w = a.w+p.w;
    *(float4*)(g_qin + t) = o;
}

__global__ void prep_kv_kernel(const float* __restrict__ mem,
                               const float* __restrict__ pos) {
    int idx = blockIdx.x * blockDim.x + threadIdx.x;
    int t = idx * 4;
    if (t >= NB*LK*DM) return;
    int d = t % DM;
    int r = t / DM;
    int k = r % LK;
    int b = r / LK;
    int src = (k*NB + b)*DM + d;
    float4 m = *(const float4*)(mem + src);
    float4 p = *(const float4*)(pos + src);
    float4 o; o.x = m.x+p.x; o.y = m.y+p.y; o.z = m.z+p.z; o.w = m.w+p.w;
    *(float4*)(g_kin + t) = o;
    *(float4*)(g_vin + t) = m;
}

/* ================== tensor-core GEMM (split-bf16, 3-pass) ================
 * C[m,n] = alpha * sum_k A[m,k] * (TRANS_B ? B[n,k] : B[k,n])
 * fp32 in/out.  A=Ah+Al, B=Bh+Bl (bf16); C ~= Ah*Bh + Al*Bh + Ah*Bl.
 * CTA tile 128x128, 8 warps (4x2), warp tile 32x64, k-step 16,
 * double-buffered smem + register prefetch.
 * M,N multiples of 128; K multiple of 16.
 * ========================================================================= */

#define APITCH 40          /* bf16 elements per A/B(NT) smem row (32 data + pad) */
#define BPITCH 136         /* bf16 elements per B(NN) smem row (128 data + pad)  */

#define LDSM4(R, addr) \
    asm volatile("ldmatrix.sync.aligned.m8n8.x4.shared.b16 {%0,%1,%2,%3}, [%4];" \
        : "=r"((R)[0]),"=r"((R)[1]),"=r"((R)[2]),"=r"((R)[3]) : "r"(addr))
#define LDSM4T(R, addr) \
    asm volatile("ldmatrix.sync.aligned.m8n8.x4.trans.shared.b16 {%0,%1,%2,%3}, [%4];" \
        : "=r"((R)[0]),"=r"((R)[1]),"=r"((R)[2]),"=r"((R)[3]) : "r"(addr))
#define MMA16816(D, A, B0, B1) \
    asm volatile("mma.sync.aligned.m16n8k16.row.col.f32.bf16.bf16.f32 " \
        "{%0,%1,%2,%3}, {%4,%5,%6,%7}, {%8,%9}, {%0,%1,%2,%3};" \
        : "+f"((D)[0]),"+f"((D)[1]),"+f"((D)[2]),"+f"((D)[3]) \
        : "r"((A)[0]),"r"((A)[1]),"r"((A)[2]),"r"((A)[3]), "r"(B0),"r"(B1))

__device__ __forceinline__ void cvt4(float4 v,
                                     __nv_bfloat162& h01, __nv_bfloat162& h23,
                                     __nv_bfloat162& l01, __nv_bfloat162& l23) {
    __nv_bfloat16 h0 = __float2bfloat16(v.x);
    __nv_bfloat16 h1 = __float2bfloat16(v.y);
    __nv_bfloat16 h2 = __float2bfloat16(v.z);
    __nv_bfloat16 h3 = __float2bfloat16(v.w);
    __nv_bfloat16 l0 = __float2bfloat16(v.x - __bfloat162float(h0));
    __nv_bfloat16 l1 = __float2bfloat16(v.y - __bfloat162float(h1));
    __nv_bfloat16 l2 = __float2bfloat16(v.z - __bfloat162float(h2));
    __nv_bfloat16 l3 = __float2bfloat16(v.w - __bfloat162float(h3));
    h01 = __halves2bfloat162(h0, h1);
    h23 = __halves2bfloat162(h2, h3);
    l01 = __halves2bfloat162(l0, l1);
    l23 = __halves2bfloat162(l2, l3);
}

template<bool TRANS_B>
__global__ void __launch_bounds__(256)
gemm_tc(const float* __restrict__ A, const float* __restrict__ B,
        float* __restrict__ C,
        int lda, int ldb, int ldc, int K, float alpha,
        long long sA0, long long sA1,
        long long sB0, long long sB1,
        long long sC0, long long sC1) {
    int z = blockIdx.z;
    int z0 = z / NH, z1 = z % NH;
    A += z0*sA0 + z1*sA1;
    B += z0*sB0 + z1*sB1;
    C += z0*sC0 + z1*sC1;

    const int m0 = blockIdx.y * 128;
    const int n0 = blockIdx.x * 128;

    const int tid  = threadIdx.x;
    const int lane = tid & 31;
    const int warp = tid >> 5;
    const int wm   = warp >> 1;   /* 0..3 */
    const int wn   = warp & 1;    /* 0..1 */

    constexpr int BSZ = TRANS_B ? 128*APITCH : 32*BPITCH;
    __shared__ __align__(16) __nv_bfloat16 As[2][128*APITCH];
    __shared__ __align__(16) __nv_bfloat16 Bs[2][BSZ];

    /* loader indices (k-major tiles: A always; B when TRANS) */
    const int la_row = tid >> 2;        /* 0..63 */
    const int la_k4  = (tid & 3) * 4;   /* 0,4,8,12 */

    float4 pa[2], pb[2];

    float acc[2][8][4];
    #pragma unroll
    for (int i = 0; i < 2; i++)
        #pragma unroll
        for (int j = 0; j < 8; j++)
            #pragma unroll
            for (int c = 0; c < 4; c++) acc[i][j][c] = 0.f;

    const int nk = K / 16;

    /* ---- global load (registers) ---- */
    auto g_load = [&](int k0) {
        pa[0] = *(const float4*)(A + (long long)(m0 + la_row     )*lda + k0 + la_k4);
        pa[1] = *(const float4*)(A + (long long)(m0 + la_row + 64)*lda + k0 + la_k4);
        if (TRANS_B) {
            pb[0] = *(const float4*)(B + (long long)(n0 + la_row     )*ldb + k0 + la_k4);
            pb[1] = *(const float4*)(B + (long long)(n0 + la_row + 64)*ldb + k0 + la_k4);
        } else {
            pb[0] = *(const float4*)(B + (long long)(k0 + (tid>>5)    )*ldb + n0 + (tid&31)*4);
            pb[1] = *(const float4*)(B + (long long)(k0 + (tid>>5) + 8)*ldb + n0 + (tid&31)*4);
        }
    };

    /* ---- registers -> smem (with fp32 -> hi/lo bf16 split) ---- */
    auto s_store = [&](int buf) {
        __nv_bfloat162 h01, h23, l01, l23;
        #pragma unroll
        for (int i = 0; i < 2; i++) {
            int row = la_row + i*64;
            cvt4(pa[i], h01, h23, l01, l23);
            __nv_bfloat16* p = &As[buf][row*APITCH + la_k4];
            *(__nv_bfloat162*)(p)      = h01;
            *(__nv_bfloat162*)(p + 2)  = h23;
            *(__nv_bfloat162*)(p + 16) = l01;
            *(__nv_bfloat162*)(p + 18) = l23;
        }
        if (TRANS_B) {
            #pragma unroll
            for (int i = 0; i < 2; i++) {
                int row = la_row + i*64;
                cvt4(pb[i], h01, h23, l01, l23);
                __nv_bfloat16* p = &Bs[buf][row*APITCH + la_k4];
                *(__nv_bfloat162*)(p)      = h01;
                *(__nv_bfloat162*)(p + 2)  = h23;
                *(__nv_bfloat162*)(p + 16) = l01;
                *(__nv_bfloat162*)(p + 18) = l23;
            }
        } else {
            #pragma unroll
            for (int i = 0; i < 2; i++) {
                int k  = (tid>>5) + i*8;
                int n4 = (tid&31)*4;
                cvt4(pb[i], h01, h23, l01, l23);
                __nv_bfloat16* p = &Bs[buf][k*BPITCH + n4];
                *(__nv_bfloat162*)(p)     = h01;
                *(__nv_bfloat162*)(p + 2) = h23;
                __nv_bfloat16* q = &Bs[buf][(k+16)*BPITCH + n4];
                *(__nv_bfloat162*)(q)     = l01;
                *(__nv_bfloat162*)(q + 2) = l23;
            }
        }
    };

    /* ---- compute one k-step from smem buffer ---- */
    auto compute = [&](int buf) {
        uint32_t a_h[2][4], a_l[2][4];
        #pragma unroll
        for (int mi = 0; mi < 2; mi++) {
            int row = wm*32 + mi*16 + (lane & 7) + ((lane >> 3) & 1)*8;
            uint32_t ad = (uint32_t)__cvta_generic_to_shared(
                &As[buf][row*APITCH + ((lane >> 4) & 1)*8]);
            LDSM4(a_h[mi], ad);
            LDSM4(a_l[mi], ad + 32);
        }
        #pragma unroll
        for (int g = 0; g < 4; g++) {
            uint32_t bh[4], bl[4];
            if (TRANS_B) {
                int n = wn*64 + g*16 + (lane & 7) + ((lane >> 4) & 1)*8;
                uint32_t bd = (uint32_t)__cvta_generic_to_shared(
                    &Bs[buf][n*APITCH + ((lane >> 3) & 1)*8]);
                LDSM4(bh, bd);
                LDSM4(bl, bd + 32);
            } else {
                int kr = (lane & 7) + ((lane >> 3) & 1)*8;
                int nc = wn*64 + g*16 + ((lane >> 4) & 1)*8;
                uint32_t bd = (uint32_t)__cvta_generic_to_shared(
                    &Bs[buf][kr*BPITCH + nc]);
                LDSM4T(bh, bd);
                LDSM4T(bl, bd + 16*BPITCH*2);
            }
            #pragma unroll
            for (int t = 0; t < 2; t++) {
                #pragma unroll
                for (int mi = 0; mi < 2; mi++) {
                    float* d = acc[mi][g*2 + t];
                    MMA16816(d, a_h[mi], bh[2*t], bh[2*t+1]);
                    MMA16816(d, a_l[mi], bh[2*t], bh[2*t+1]);
                    MMA16816(d, a_h[mi], bl[2*t], bl[2*t+1]);
                }
            }
        }
    };

    g_load(0);
    s_store(0);
    __syncthreads();

    for (int ks = 0; ks < nk; ks++) {
        int buf = ks & 1;
        bool more = (ks + 1) < nk;
        if (more) g_load((ks + 1) * 16);
        compute(buf);
        if (more) s_store(buf ^ 1);
        __syncthreads();
    }

    /* ---- epilogue ---- */
    #pragma unroll
    for (int mi = 0; mi < 2; mi++) {
        #pragma unroll
        for (int nj = 0; nj < 8; nj++) {
            int row = m0 + wm*32 + mi*16 + (lane >> 2);
            int col = n0 + wn*64 + nj*8 + (lane & 3)*2;
            float2 v0; v0.x = alpha*acc[mi][nj][0]; v0.y = alpha*acc[mi][nj][1];
            float2 v1; v1.x = alpha*acc[mi][nj][2]; v1.y = alpha*acc[mi][nj][3];
            *(float2*)(C + (long long)row*ldc + col)       = v0;
            *(float2*)(C + (long long)(row+8)*ldc + col)   = v1;
        }
    }
}

/* ---------------- fused softmax (in-place) + head-mean to d_out ---------- */
__device__ __forceinline__ float blk_reduce_max(float v, float* red) {
    red[threadIdx.x] = v; __syncthreads();
    for (int s = 128; s > 0; s >>= 1) {
        if (threadIdx.x < s) red[threadIdx.x] = fmaxf(red[threadIdx.x], red[threadIdx.x+s]);
        __syncthreads();
    }
    float r = red[0]; __syncthreads(); return r;
}
__device__ __forceinline__ float blk_reduce_sum(float v, float* red) {
    red[threadIdx.x] = v; __syncthreads();
    for (int s = 128; s > 0; s >>= 1) {
        if (threadIdx.x < s) red[threadIdx.x] += red[threadIdx.x+s];
        __syncthreads();
    }
    float r = red[0]; __syncthreads(); return r;
}

__global__ void __launch_bounds__(256)
softmax_mean_kernel(float* __restrict__ out_mean) {
    const int row = blockIdx.x;      /* b*LQ + q */
    const int b = row / LQ;
    const int q = row % LQ;
    const int tid = threadIdx.x;
    __shared__ float red[256];

    float mean_acc[LK/256];
    #pragma unroll
    for (int i = 0; i < LK/256; i++) mean_acc[i] = 0.f;

    for (int h = 0; h < NH; h++) {
        float* base = g_logits + ((long long)((b*NH + h)*LQ + q)) * LK;
        float v[LK/256];
        float mx = -1e30f;
        #pragma unroll
        for (int i = 0; i < LK/256; i++) {
            v[i] = base[i*256 + tid];
            mean_acc[i] += v[i];
            mx = fmaxf(mx, v[i]);
        }
        mx = blk_reduce_max(mx, red);
        float s = 0.f;
        #pragma unroll
        for (int i = 0; i < LK/256; i++) { v[i] = expf(v[i] - mx); s += v[i]; }
        s = blk_reduce_sum(s, red);
        float inv = 1.f / s;
        #pragma unroll
        for (int i = 0; i < LK/256; i++) base[i*256 + tid] = v[i] * inv;
    }
    float* mdst = out_mean + (long long)row * LK;
    #pragma unroll
    for (int i = 0; i < LK/256; i++) mdst[i*256 + tid] = mean_acc[i] * 0.25f;
}

/* ---------------- residual + LayerNorm, write y to d_out ----------------- */
__global__ void __launch_bounds__(256)
ln_kernel(const float* __restrict__ tgt,
          const float* __restrict__ gamma,
          const float* __restrict__ beta,
          float* __restrict__ y) {
    const int row = blockIdx.x;
    const int b = row / LQ;
    const int q = row % LQ;
    const int d = threadIdx.x;
    __shared__ float red[256];

    float x = g_fc[row*DM + d] + tgt[(q*NB + b)*DM + d];
    float mu = blk_reduce_sum(x, red) * (1.f/DM);
    float diff = x - mu;
    float var = blk_reduce_sum(diff*diff, red) * (1.f/DM);
    y[(q*NB + b)*DM + d] = diff * rsqrtf(var + 1e-5f) * gamma[d] + beta[d];
}

/* ---------------- launch ------------------------------------------------- */
extern "C" void kernel_launch(void* const* d_in, const int* in_sizes, int n_in,
                              void* d_out, int out_size) {
    const float* tgt  = (const float*)d_in[0];
    const float* mem  = (const float*)d_in[1];
    const float* pos  = (const float*)d_in[2];
    const float* qpos = (const float*)d_in[3];
    const float* Wq   = (const float*)d_in[4];
    const float* Wk   = (const float*)d_in[5];
    const float* Wv   = (const float*)d_in[6];
    const float* Wfc  = (const float*)d_in[7];
    const float* ln_g = (const float*)d_in[8];
    const float* ln_b = (const float*)d_in[9];
    float* out = (float*)d_out;

    float *qin, *kin, *vin, *Qh, *Kh, *Vh, *logits, *O, *fc;
    cudaGetSymbolAddress((void**)&qin,    g_qin);
    cudaGetSymbolAddress((void**)&kin,    g_kin);
    cudaGetSymbolAddress((void**)&vin,    g_vin);
    cudaGetSymbolAddress((void**)&Qh,     g_Qh);
    cudaGetSymbolAddress((void**)&Kh,     g_Kh);
    cudaGetSymbolAddress((void**)&Vh,     g_Vh);
    cudaGetSymbolAddress((void**)&logits, g_logits);
    cudaGetSymbolAddress((void**)&O,      g_O);
    cudaGetSymbolAddress((void**)&fc,     g_fc);

    /* 1) transpose + pos adds */
    prep_q_kernel <<<(NB*LQ*DM/4 + 255)/256, 256>>>(tgt, qpos);
    prep_kv_kernel<<<(NB*LK*DM/4 + 255)/256, 256>>>(mem, pos);

    /* 2) projections (NT): X[M,256] @ W[1024,256]^T */
    {
        dim3 g(HD/128, (NB*LQ)/128, 1);
        gemm_tc<true><<<g, 256>>>(qin, Wq, Qh, DM, DM, HD, DM, 1.f,
                                  0,0, 0,0, 0,0);
    }
    {
        dim3 g(HD/128, (NB*LK)/128, 1);
        gemm_tc<true><<<g, 256>>>(kin, Wk, Kh, DM, DM, HD, DM, 1.f,
                                  0,0, 0,0, 0,0);
        gemm_tc<true><<<g, 256>>>(vin, Wv, Vh, DM, DM, HD, DM, 1.f,
                                  0,0, 0,0, 0,0);
    }

    /* 3) logits = (1/16) * Qh @ Kh^T   (batched over b,h; z = b*NH+h) */
    {
        dim3 g(LK/128, LQ/128, NB*NH);
        gemm_tc<true><<<g, 256>>>(Qh, Kh, logits,
                                  HD, HD, LK, DM, 0.0625f,
                                  (long long)LQ*HD, DM,
                                  (long long)LK*HD, DM,
                                  (long long)NH*LQ*LK, (long long)LQ*LK);
    }

    /* 4) softmax in place + head-mean of logits into d_out tail */
    softmax_mean_kernel<<<NB*LQ, 256>>>(out + Y_SIZE);

    /* 5) O = attn @ Vh (NN, batched) */
    {
        dim3 g(DM/128, LQ/128, NB*NH);
        gemm_tc<false><<<g, 256>>>(logits, Vh, O,
                                   LK, HD, HD, LK, 1.f,
                                   (long long)NH*LQ*LK, (long long)LQ*LK,
                                   (long long)LK*HD, DM,
                                   (long long)LQ*HD, DM);
    }

    /* 6) fc (NT): O[8192,1024] @ Wfc[256,1024]^T */
    {
        dim3 g(DM/128, (NB*LQ)/128, 1);
        gemm_tc<true><<<g, 256>>>(O, Wfc, fc, HD, HD, DM, HD, 1.f,
                                  0,0, 0,0, 0,0);
    }

    /* 7) residual + LayerNorm -> y at d_out head */
    ln_kernel<<<NB*LQ, 256>>>(tgt, ln_g, ln_b, out);
}